// round 9
// baseline (speedup 1.0000x reference)
#include <cuda_runtime.h>
#include <cuda_fp16.h>
#include <cstdint>

#define NN   50000
#define NE   1600000
#define NG   512
#define IND  64
#define HID  128
#define OUTD 10
#define SCAN_B 1024
#define NBLK ((NN + SCAN_B - 1) / SCAN_B)   // 49
#define FLAG_AGG (1 << 30)
#define FLAG_INC (2 << 30)
#define VAL_MASK ((1 << 30) - 1)
#define FULL 0xffffffffu

// ---------------- scratch (static __device__, zero-initialized; every kernel
// restores what it consumes so the graph can be replayed indefinitely) --------
__device__ int            g_is64;
__device__ float          g_deg[NN];     // starts 0; scan resets after dinv
__device__ float          g_dinv[NN];
__device__ int            g_count[NN];   // starts 0; scan resets
__device__ int            g_rowptr[NN + 1];
__device__ unsigned short g_rank[NE];    // edge rank within dst bucket
__device__ unsigned       g_edge[NE];    // packed: src u16 | ew fp16 << 16
__device__ int            g_desc[NBLK];  // lookback descriptors; last block resets
__device__ int            g_done;        // ticket counter; last block resets
__device__ int            g_gcount[NG];  // starts 0; scan resets
__device__ int            g_gptr[NG + 1];
__device__ __half         g_xh[NN * IND];   // fp16 x; rewritten by histpre, scaled by scan
__device__ __half         g_w1h[IND * HID];
__device__ __half         g_w2h[HID * HID];
__device__ __half         g_axh[NN * IND];  // fp16 dinv.*(S @ xs)
__device__ __half         g_h2h[NN * HID];  // fp16 dinv.*(a1 @ W2)
__device__ __half         g_a2h[NN * HID];  // fp16 relu(S @ h2 + b2)

// ---------------- fused: is64 detect + histograms (+rank) + fp16 conversions -
__global__ void k_histpre(const void* __restrict__ ei, const void* __restrict__ batch,
                          const float* __restrict__ ew, const float* __restrict__ x,
                          const float* __restrict__ W1, const float* __restrict__ W2) {
    __shared__ int s_flag;
    int tid = threadIdx.x;
    if (tid == 0) s_flag = 1;
    __syncthreads();
    if (tid < 128) {
        if (((const unsigned*)ei)[2 * tid + 1] != 0u) s_flag = 0;  // benign race
    }
    __syncthreads();
    int is64 = s_flag;
    if (blockIdx.x == 0 && tid == 0) g_is64 = is64;   // publish for k_scatter

    int i = blockIdx.x * blockDim.x + tid;
    if (i < NE) {
        int d = is64 ? (int)((const long long*)ei)[NE + i] : ((const int*)ei)[NE + i];
        atomicAdd(&g_deg[d], ew[i]);
        g_rank[i] = (unsigned short)atomicAdd(&g_count[d], 1);
    }
    if (i < NN) {
        int b = is64 ? (int)((const long long*)batch)[i] : ((const int*)batch)[i];
        atomicAdd(&g_gcount[b], 1);
    }
    if (i < NN * IND / 2) {
        float2 v = ((const float2*)x)[i];
        ((__half2*)g_xh)[i] = __floats2half2_rn(v.x, v.y);
    }
    if (i < IND * HID / 2) {
        float2 v = ((const float2*)W1)[i];
        ((__half2*)g_w1h)[i] = __floats2half2_rn(v.x, v.y);
    }
    if (i < HID * HID / 2) {
        float2 v = ((const float2*)W2)[i];
        ((__half2*)g_w2h)[i] = __floats2half2_rn(v.x, v.y);
    }
}

// ---------------- single-pass scan: counts->rowptr, dinv, gptr, xh scaling ---
__global__ void __launch_bounds__(SCAN_B) k_scan() {
    __shared__ int ws[32];
    __shared__ int ws2[16];
    __shared__ int s_excl;
    int tid = threadIdx.x, lane = tid & 31, warp = tid >> 5;
    int b = blockIdx.x;
    int idx = b * SCAN_B + tid;
    int v = 0;
    if (idx < NN) {
        v = g_count[idx];
        g_count[idx] = 0;                           // restore
        g_dinv[idx] = rsqrtf(1.0f + g_deg[idx]);    // self-loop weight 1
        g_deg[idx] = 0.0f;                          // restore
    }
    int xi = v;
    #pragma unroll
    for (int off = 1; off < 32; off <<= 1) {
        int t = __shfl_up_sync(FULL, xi, off);
        if (lane >= off) xi += t;
    }
    if (lane == 31) ws[warp] = xi;
    __syncthreads();
    if (warp == 0) {
        int y = ws[lane];
        #pragma unroll
        for (int off = 1; off < 32; off <<= 1) {
            int t = __shfl_up_sync(FULL, y, off);
            if (lane >= off) y += t;
        }
        ws[lane] = y;
        int total = __shfl_sync(FULL, y, 31);
        if (lane == 0) {
            *((volatile int*)&g_desc[b]) = FLAG_AGG | total;
            __threadfence();
        }
        int excl = 0;
        if (b > 0) {
            int p = b - 1;
            for (;;) {
                int j = p - lane;
                int d;
                do {
                    d = (j >= 0) ? *((volatile int*)&g_desc[j]) : FLAG_INC;
                } while (__any_sync(FULL, d == 0));
                unsigned incmask = __ballot_sync(FULL, (d & FLAG_INC) != 0);
                if (incmask) {
                    int fi = __ffs(incmask) - 1;
                    int c = (lane <= fi) ? (d & VAL_MASK) : 0;
                    #pragma unroll
                    for (int off = 16; off > 0; off >>= 1)
                        c += __shfl_down_sync(FULL, c, off);
                    excl += __shfl_sync(FULL, c, 0);
                    break;
                } else {
                    int c = d & VAL_MASK;
                    #pragma unroll
                    for (int off = 16; off > 0; off >>= 1)
                        c += __shfl_down_sync(FULL, c, off);
                    excl += __shfl_sync(FULL, c, 0);
                    p -= 32;
                }
            }
        }
        if (lane == 0) {
            *((volatile int*)&g_desc[b]) = FLAG_INC | (excl + total);
            __threadfence();
            s_excl = excl;
        }
    }
    __syncthreads();
    int excl = s_excl;
    int incl = xi + (warp ? ws[warp - 1] : 0);
    if (idx < NN) g_rowptr[idx] = excl + incl - v;
    if (b == 0 && tid == 0) g_rowptr[NN] = NE;

    // block 0: gptr scan over NG=512 bins
    int gv = 0;
    if (b == 0 && tid < NG) { gv = g_gcount[tid]; g_gcount[tid] = 0; }
    int x2 = gv;
    #pragma unroll
    for (int off = 1; off < 32; off <<= 1) {
        int t = __shfl_up_sync(FULL, x2, off);
        if (lane >= off) x2 += t;
    }
    if (b == 0 && tid < NG && lane == 31) ws2[warp] = x2;
    __syncthreads();
    if (b == 0 && warp == 0 && lane < 16) {
        int y = ws2[lane];
        #pragma unroll
        for (int off = 1; off < 16; off <<= 1) {
            int t = __shfl_up_sync(0xffffu, y, off);
            if (lane >= off) y += t;
        }
        ws2[lane] = y;
    }
    __syncthreads();
    if (b == 0 && tid < NG)
        g_gptr[tid] = x2 + (warp ? ws2[warp - 1] : 0) - gv;
    if (b == 0 && tid == 0) g_gptr[NG] = NN;

    // ---- scale this block's node features: xh[node] *= dinv[node] ----------
    // (dinv for nodes of this block written above; __syncthreads passed)
    {
        int node0 = b * SCAN_B;
        int nloc  = min(SCAN_B, NN - node0);
        if (nloc > 0) {
            __half2* xp = (__half2*)g_xh + (size_t)node0 * 32;
            int total2 = nloc * 32;              // half2 count
            for (int i = tid; i < total2; i += SCAN_B) {
                float dn = g_dinv[node0 + (i >> 5)];   // warp-uniform
                float2 vv = __half22float2(xp[i]);
                xp[i] = __floats2half2_rn(vv.x * dn, vv.y * dn);
            }
        }
    }

    __syncthreads();
    if (tid == 0) {
        int t = atomicAdd(&g_done, 1);
        if (t == NBLK - 1) {
            #pragma unroll 1
            for (int i = 0; i < NBLK; i++) g_desc[i] = 0;
            g_done = 0;
            __threadfence();
        }
    }
}

// ---------------- scatter (atomic-free, pure edge placement) -----------------
__global__ void k_scatter(const void* __restrict__ ei, const float* __restrict__ ew) {
    int i = blockIdx.x * blockDim.x + threadIdx.x;
    if (i >= NE) return;
    int s, d;
    if (g_is64) {
        const long long* p = (const long long*)ei;
        s = (int)p[i]; d = (int)p[NE + i];
    } else {
        const int* p = (const int*)ei;
        s = p[i]; d = p[NE + i];
    }
    int pos = g_rowptr[d] + (int)g_rank[i];
    g_edge[pos] = (unsigned)s |
                  ((unsigned)__half_as_ushort(__float2half_rn(ew[i])) << 16);
}

// ---------------- layer-1 aggregation: axh = dinv .* (S @ xs), 64-dim --------
__global__ void __launch_bounds__(256) k_aggx() {
    int node = (blockIdx.x * 256 + threadIdx.x) >> 5;
    int lane = threadIdx.x & 31;
    if (node >= NN) return;
    float dn = g_dinv[node];
    float2 self = __half22float2(((const __half2*)g_xh)[node * 32 + lane]);
    float2 acc = self;   // self term: dn * xs[node] = dn^2 * x[node]
    int e   = g_rowptr[node];
    int end = g_rowptr[node + 1];
    #pragma unroll 4
    for (; e < end; e++) {
        unsigned rec = __ldg(&g_edge[e]);
        int src  = rec & 0xFFFFu;
        float w  = __half2float(__ushort_as_half((unsigned short)(rec >> 16)));
        float2 hs = __half22float2(((const __half2*)g_xh)[src * 32 + lane]);
        acc.x += hs.x * w; acc.y += hs.y * w;
    }
    ((__half2*)g_axh)[node * 32 + lane] = __floats2half2_rn(acc.x * dn, acc.y * dn);
}

// ---------------- fused double GEMM: h2h = dinv .* ((relu(ax@W1+b1)) @ W2) ----
__global__ void __launch_bounds__(256) k_gemmf(const float* __restrict__ bias) {
    constexpr int LDU = 136;           // halves (128+8 pad)
    constexpr int KC  = 32;
    __shared__ __half U[128 * LDU];    // 34.8 KB: stage-1 A, then a1 tile
    __shared__ __half Bs[KC * LDU];    //  8.7 KB: W chunks
    int tid = threadIdx.x;
    int row0 = blockIdx.x * 128;
    int warp = tid >> 5, lane = tid & 31;
    int wm = (warp & 3) * 32;
    int wn = (warp >> 2) * 64;
    float acc[2][8][4];

    #pragma unroll
    for (int mi = 0; mi < 2; mi++)
        #pragma unroll
        for (int nj = 0; nj < 8; nj++)
            #pragma unroll
            for (int q = 0; q < 4; q++) acc[mi][nj][q] = 0.f;

    for (int i = tid; i < 128 * IND / 8; i += 256) {
        int r = i >> 3, c = (i & 7) * 8;
        uint4 v = make_uint4(0u, 0u, 0u, 0u);
        if (row0 + r < NN)
            v = ((const uint4*)g_axh)[(row0 + r) * (IND / 8) + c / 8];
        *(uint4*)&U[r * LDU + c] = v;
    }
    #pragma unroll 1
    for (int kc = 0; kc < IND; kc += KC) {
        __syncthreads();
        for (int i = tid; i < KC * 128 / 8; i += 256) {
            int r = i >> 4, c = (i & 15) * 8;
            *(uint4*)&Bs[r * LDU + c] = ((const uint4*)g_w1h)[((kc + r) * 128 + c) / 8];
        }
        __syncthreads();
        #pragma unroll
        for (int k = 0; k < KC; k += 16) {
            uint32_t a[2][4], b[4][4];
            #pragma unroll
            for (int mi = 0; mi < 2; mi++) {
                uint32_t addr = (uint32_t)__cvta_generic_to_shared(
                    &U[(wm + mi * 16 + (lane & 15)) * LDU + kc + k + 8 * (lane >> 4)]);
                asm volatile("ldmatrix.sync.aligned.m8n8.x4.shared.b16 {%0,%1,%2,%3}, [%4];"
                             : "=r"(a[mi][0]), "=r"(a[mi][1]), "=r"(a[mi][2]), "=r"(a[mi][3])
                             : "r"(addr));
            }
            #pragma unroll
            for (int ni = 0; ni < 4; ni++) {
                uint32_t addr = (uint32_t)__cvta_generic_to_shared(
                    &Bs[(k + (lane & 15)) * LDU + wn + ni * 16 + 8 * (lane >> 4)]);
                asm volatile("ldmatrix.sync.aligned.m8n8.x4.trans.shared.b16 {%0,%1,%2,%3}, [%4];"
                             : "=r"(b[ni][0]), "=r"(b[ni][1]), "=r"(b[ni][2]), "=r"(b[ni][3])
                             : "r"(addr));
            }
            #pragma unroll
            for (int mi = 0; mi < 2; mi++)
                #pragma unroll
                for (int nj = 0; nj < 8; nj++) {
                    uint32_t b0 = b[nj >> 1][(nj & 1) * 2 + 0];
                    uint32_t b1 = b[nj >> 1][(nj & 1) * 2 + 1];
                    asm volatile(
                        "mma.sync.aligned.m16n8k16.row.col.f32.f16.f16.f32 "
                        "{%0,%1,%2,%3}, {%4,%5,%6,%7}, {%8,%9}, {%0,%1,%2,%3};"
                        : "+f"(acc[mi][nj][0]), "+f"(acc[mi][nj][1]),
                          "+f"(acc[mi][nj][2]), "+f"(acc[mi][nj][3])
                        : "r"(a[mi][0]), "r"(a[mi][1]), "r"(a[mi][2]), "r"(a[mi][3]),
                          "r"(b0), "r"(b1));
                }
        }
    }
    __syncthreads();
    #pragma unroll
    for (int mi = 0; mi < 2; mi++)
        #pragma unroll
        for (int nj = 0; nj < 8; nj++) {
            int col = wn + nj * 8 + 2 * (lane & 3);
            float bx = bias[col], by = bias[col + 1];
            #pragma unroll
            for (int h = 0; h < 2; h++) {
                int r = wm + mi * 16 + (lane >> 2) + h * 8;
                float v0 = fmaxf(acc[mi][nj][2 * h + 0] + bx, 0.f);
                float v1 = fmaxf(acc[mi][nj][2 * h + 1] + by, 0.f);
                *(__half2*)&U[r * LDU + col] = __floats2half2_rn(v0, v1);
                acc[mi][nj][2 * h + 0] = 0.f;
                acc[mi][nj][2 * h + 1] = 0.f;
            }
        }
    #pragma unroll 1
    for (int kc = 0; kc < HID; kc += KC) {
        __syncthreads();
        for (int i = tid; i < KC * 128 / 8; i += 256) {
            int r = i >> 4, c = (i & 15) * 8;
            *(uint4*)&Bs[r * LDU + c] = ((const uint4*)g_w2h)[((kc + r) * 128 + c) / 8];
        }
        __syncthreads();
        #pragma unroll
        for (int k = 0; k < KC; k += 16) {
            uint32_t a[2][4], b[4][4];
            #pragma unroll
            for (int mi = 0; mi < 2; mi++) {
                uint32_t addr = (uint32_t)__cvta_generic_to_shared(
                    &U[(wm + mi * 16 + (lane & 15)) * LDU + kc + k + 8 * (lane >> 4)]);
                asm volatile("ldmatrix.sync.aligned.m8n8.x4.shared.b16 {%0,%1,%2,%3}, [%4];"
                             : "=r"(a[mi][0]), "=r"(a[mi][1]), "=r"(a[mi][2]), "=r"(a[mi][3])
                             : "r"(addr));
            }
            #pragma unroll
            for (int ni = 0; ni < 4; ni++) {
                uint32_t addr = (uint32_t)__cvta_generic_to_shared(
                    &Bs[(k + (lane & 15)) * LDU + wn + ni * 16 + 8 * (lane >> 4)]);
                asm volatile("ldmatrix.sync.aligned.m8n8.x4.trans.shared.b16 {%0,%1,%2,%3}, [%4];"
                             : "=r"(b[ni][0]), "=r"(b[ni][1]), "=r"(b[ni][2]), "=r"(b[ni][3])
                             : "r"(addr));
            }
            #pragma unroll
            for (int mi = 0; mi < 2; mi++)
                #pragma unroll
                for (int nj = 0; nj < 8; nj++) {
                    uint32_t b0 = b[nj >> 1][(nj & 1) * 2 + 0];
                    uint32_t b1 = b[nj >> 1][(nj & 1) * 2 + 1];
                    asm volatile(
                        "mma.sync.aligned.m16n8k16.row.col.f32.f16.f16.f32 "
                        "{%0,%1,%2,%3}, {%4,%5,%6,%7}, {%8,%9}, {%0,%1,%2,%3};"
                        : "+f"(acc[mi][nj][0]), "+f"(acc[mi][nj][1]),
                          "+f"(acc[mi][nj][2]), "+f"(acc[mi][nj][3])
                        : "r"(a[mi][0]), "r"(a[mi][1]), "r"(a[mi][2]), "r"(a[mi][3]),
                          "r"(b0), "r"(b1));
                }
        }
    }
    #pragma unroll
    for (int mi = 0; mi < 2; mi++)
        #pragma unroll
        for (int nj = 0; nj < 8; nj++) {
            int col = wn + nj * 8 + 2 * (lane & 3);
            #pragma unroll
            for (int h = 0; h < 2; h++) {
                int r = row0 + wm + mi * 16 + (lane >> 2) + h * 8;
                if (r < NN) {
                    float dn = g_dinv[r];
                    float v0 = acc[mi][nj][2 * h + 0] * dn;
                    float v1 = acc[mi][nj][2 * h + 1] * dn;
                    ((__half2*)g_h2h)[(r * 128 + col) >> 1] = __floats2half2_rn(v0, v1);
                }
            }
        }
}

// ---------------- layer-2 aggregation: a2h = fp16(relu(S @ h2 + b2)) ---------
__global__ void __launch_bounds__(256) k_agg128(const float* __restrict__ bias) {
    int node = (blockIdx.x * 256 + threadIdx.x) >> 5;
    int lane = threadIdx.x & 31;
    if (node >= NN) return;
    float dn = g_dinv[node];
    uint2 sv = ((const uint2*)g_h2h)[node * 32 + lane];
    float2 s0 = __half22float2(*(__half2*)&sv.x);
    float2 s1 = __half22float2(*(__half2*)&sv.y);
    float4 acc = make_float4(s0.x, s0.y, s1.x, s1.y);
    int e   = g_rowptr[node];
    int end = g_rowptr[node + 1];
    #pragma unroll 4
    for (; e < end; e++) {
        unsigned rec = __ldg(&g_edge[e]);
        int src  = rec & 0xFFFFu;
        float w  = __half2float(__ushort_as_half((unsigned short)(rec >> 16)));
        uint2 hv = ((const uint2*)g_h2h)[src * 32 + lane];
        float2 f0 = __half22float2(*(__half2*)&hv.x);
        float2 f1 = __half22float2(*(__half2*)&hv.y);
        acc.x += f0.x * w; acc.y += f0.y * w;
        acc.z += f1.x * w; acc.w += f1.y * w;
    }
    float4 b = ((const float4*)bias)[lane];
    acc.x = fmaxf(acc.x * dn + b.x, 0.f);
    acc.y = fmaxf(acc.y * dn + b.y, 0.f);
    acc.z = fmaxf(acc.z * dn + b.z, 0.f);
    acc.w = fmaxf(acc.w * dn + b.w, 0.f);
    uint2 pk;
    __half2 h0 = __floats2half2_rn(acc.x, acc.y);
    __half2 h1 = __floats2half2_rn(acc.z, acc.w);
    pk.x = *(unsigned*)&h0;
    pk.y = *(unsigned*)&h1;
    ((uint2*)g_a2h)[node * 32 + lane] = pk;
}

// ---------------- fused pool (sorted batch -> contiguous ranges) + MLP head --
__global__ void __launch_bounds__(128) k_poolmlp(const float* __restrict__ Wm1,
                                                 const float* __restrict__ bm1,
                                                 const float* __restrict__ Wm2,
                                                 const float* __restrict__ bm2,
                                                 float* __restrict__ out) {
    int g = blockIdx.x;
    int tid = threadIdx.x;
    __shared__ float ps[HID];
    __shared__ float zs[HID];
    int n0 = g_gptr[g], n1 = g_gptr[g + 1];
    float acc = 0.f;
    for (int n = n0; n < n1; n++)
        acc += __half2float(g_a2h[n * HID + tid]);
    ps[tid] = acc;
    __syncthreads();
    float z = bm1[tid];
    #pragma unroll 8
    for (int k = 0; k < HID; k++) z += ps[k] * Wm1[k * HID + tid];
    zs[tid] = fmaxf(z, 0.f);
    __syncthreads();
    if (tid < OUTD) {
        float a = bm2[tid];
        #pragma unroll 8
        for (int k = 0; k < HID; k++) a += zs[k] * Wm2[k * OUTD + tid];
        out[g * OUTD + tid] = a;
    }
}

// ---------------- launch ----------------
extern "C" void kernel_launch(void* const* d_in, const int* in_sizes, int n_in,
                              void* d_out, int out_size) {
    const float* x   = (const float*)d_in[0];
    const void*  ei  = d_in[1];
    const void*  bt  = d_in[2];
    const float* ew  = (const float*)d_in[3];
    const float* W1  = (const float*)d_in[4];
    const float* b1  = (const float*)d_in[5];
    const float* W2  = (const float*)d_in[6];
    const float* b2  = (const float*)d_in[7];
    const float* Wm1 = (const float*)d_in[8];
    const float* bm1 = (const float*)d_in[9];
    const float* Wm2 = (const float*)d_in[10];
    const float* bm2 = (const float*)d_in[11];
    float* out = (float*)d_out;

    k_histpre<<<(NE + 255) / 256, 256>>>(ei, bt, ew, x, W1, W2);
    k_scan<<<NBLK, SCAN_B>>>();
    k_scatter<<<(NE + 255) / 256, 256>>>(ei, ew);
    k_aggx<<<(NN * 32 + 255) / 256, 256>>>();
    k_gemmf<<<(NN + 127) / 128, 256>>>(b1);
    k_agg128<<<(NN * 32 + 255) / 256, 256>>>(b2);
    k_poolmlp<<<NG, 128>>>(Wm1, bm1, Wm2, bm2, out);
}

// round 10
// speedup vs baseline: 1.0889x; 1.0889x over previous
#include <cuda_runtime.h>
#include <cuda_fp16.h>
#include <cstdint>

#define NN   50000
#define NE   1600000
#define NG   512
#define IND  64
#define HID  128
#define OUTD 10
#define SCAN_B 1024
#define NBLK ((NN + SCAN_B - 1) / SCAN_B)   // 49
#define FLAG_AGG (1 << 30)
#define FLAG_INC (2 << 30)
#define VAL_MASK ((1 << 30) - 1)
#define FULL 0xffffffffu

// ---------------- scratch (static __device__, zero-initialized; every kernel
// restores what it consumes so the graph can be replayed indefinitely) --------
__device__ int            g_is64;
__device__ float          g_deg[NN];     // starts 0; scan resets after dinv
__device__ float          g_dinv[NN];
__device__ int            g_count[NN];   // starts 0; scan resets
__device__ int            g_rowptr[NN + 1];
__device__ unsigned short g_rank[NE];    // edge rank within dst bucket
__device__ unsigned       g_edge[NE];    // packed: src u16 | ew fp16 << 16
__device__ int            g_desc[NBLK];  // lookback descriptors; last block resets
__device__ int            g_done;        // ticket counter; last block resets
__device__ int            g_gcount[NG];  // starts 0; scan resets
__device__ int            g_gptr[NG + 1];
__device__ __half         g_xh[NN * IND];   // fp16 x; scaled by dinv[row] in scatter
__device__ __half         g_w1h[IND * HID];
__device__ __half         g_w2h[HID * HID];
__device__ __half         g_axh[NN * IND];  // fp16 dinv.*(S @ xs)
__device__ __half         g_h2h[NN * HID];  // fp16 dinv.*(a1 @ W2)
__device__ __half         g_a2h[NN * HID];  // fp16 relu(S @ h2 + b2)

// ---------------- fused: is64 detect + histograms (+rank) + fp16 conversions -
__global__ void k_histpre(const void* __restrict__ ei, const void* __restrict__ batch,
                          const float* __restrict__ ew, const float* __restrict__ x,
                          const float* __restrict__ W1, const float* __restrict__ W2) {
    __shared__ int s_flag;
    int tid = threadIdx.x;
    if (tid == 0) s_flag = 1;
    __syncthreads();
    if (tid < 128) {
        if (((const unsigned*)ei)[2 * tid + 1] != 0u) s_flag = 0;  // benign race
    }
    __syncthreads();
    int is64 = s_flag;
    if (blockIdx.x == 0 && tid == 0) g_is64 = is64;   // publish for k_scatter

    int i = blockIdx.x * blockDim.x + tid;
    if (i < NE) {
        int d = is64 ? (int)((const long long*)ei)[NE + i] : ((const int*)ei)[NE + i];
        atomicAdd(&g_deg[d], ew[i]);
        g_rank[i] = (unsigned short)atomicAdd(&g_count[d], 1);
    }
    if (i < NN) {
        int b = is64 ? (int)((const long long*)batch)[i] : ((const int*)batch)[i];
        atomicAdd(&g_gcount[b], 1);
    }
    if (i < NN * IND / 2) {
        float2 v = ((const float2*)x)[i];
        ((__half2*)g_xh)[i] = __floats2half2_rn(v.x, v.y);
    }
    if (i < IND * HID / 2) {
        float2 v = ((const float2*)W1)[i];
        ((__half2*)g_w1h)[i] = __floats2half2_rn(v.x, v.y);
    }
    if (i < HID * HID / 2) {
        float2 v = ((const float2*)W2)[i];
        ((__half2*)g_w2h)[i] = __floats2half2_rn(v.x, v.y);
    }
}

// ---------------- single-pass scan: counts->rowptr, dinv, gptr ---------------
__global__ void __launch_bounds__(SCAN_B) k_scan() {
    __shared__ int ws[32];
    __shared__ int ws2[16];
    __shared__ int s_excl;
    int tid = threadIdx.x, lane = tid & 31, warp = tid >> 5;
    int b = blockIdx.x;
    int idx = b * SCAN_B + tid;
    int v = 0;
    if (idx < NN) {
        v = g_count[idx];
        g_count[idx] = 0;                           // restore
        g_dinv[idx] = rsqrtf(1.0f + g_deg[idx]);    // self-loop weight 1
        g_deg[idx] = 0.0f;                          // restore
    }
    int xi = v;
    #pragma unroll
    for (int off = 1; off < 32; off <<= 1) {
        int t = __shfl_up_sync(FULL, xi, off);
        if (lane >= off) xi += t;
    }
    if (lane == 31) ws[warp] = xi;
    __syncthreads();
    if (warp == 0) {
        int y = ws[lane];
        #pragma unroll
        for (int off = 1; off < 32; off <<= 1) {
            int t = __shfl_up_sync(FULL, y, off);
            if (lane >= off) y += t;
        }
        ws[lane] = y;
        int total = __shfl_sync(FULL, y, 31);
        if (lane == 0) {
            *((volatile int*)&g_desc[b]) = FLAG_AGG | total;
            __threadfence();
        }
        int excl = 0;
        if (b > 0) {
            int p = b - 1;
            for (;;) {
                int j = p - lane;
                int d;
                do {
                    d = (j >= 0) ? *((volatile int*)&g_desc[j]) : FLAG_INC;
                } while (__any_sync(FULL, d == 0));
                unsigned incmask = __ballot_sync(FULL, (d & FLAG_INC) != 0);
                if (incmask) {
                    int fi = __ffs(incmask) - 1;
                    int c = (lane <= fi) ? (d & VAL_MASK) : 0;
                    #pragma unroll
                    for (int off = 16; off > 0; off >>= 1)
                        c += __shfl_down_sync(FULL, c, off);
                    excl += __shfl_sync(FULL, c, 0);
                    break;
                } else {
                    int c = d & VAL_MASK;
                    #pragma unroll
                    for (int off = 16; off > 0; off >>= 1)
                        c += __shfl_down_sync(FULL, c, off);
                    excl += __shfl_sync(FULL, c, 0);
                    p -= 32;
                }
            }
        }
        if (lane == 0) {
            *((volatile int*)&g_desc[b]) = FLAG_INC | (excl + total);
            __threadfence();
            s_excl = excl;
        }
    }
    __syncthreads();
    int excl = s_excl;
    int incl = xi + (warp ? ws[warp - 1] : 0);
    if (idx < NN) g_rowptr[idx] = excl + incl - v;
    if (b == 0 && tid == 0) g_rowptr[NN] = NE;

    // block 0: gptr scan over NG=512 bins
    int gv = 0;
    if (b == 0 && tid < NG) { gv = g_gcount[tid]; g_gcount[tid] = 0; }
    int x2 = gv;
    #pragma unroll
    for (int off = 1; off < 32; off <<= 1) {
        int t = __shfl_up_sync(FULL, x2, off);
        if (lane >= off) x2 += t;
    }
    if (b == 0 && tid < NG && lane == 31) ws2[warp] = x2;
    __syncthreads();
    if (b == 0 && warp == 0 && lane < 16) {
        int y = ws2[lane];
        #pragma unroll
        for (int off = 1; off < 16; off <<= 1) {
            int t = __shfl_up_sync(0xffffu, y, off);
            if (lane >= off) y += t;
        }
        ws2[lane] = y;
    }
    __syncthreads();
    if (b == 0 && tid < NG)
        g_gptr[tid] = x2 + (warp ? ws2[warp - 1] : 0) - gv;
    if (b == 0 && tid == 0) g_gptr[NG] = NN;

    __syncthreads();
    if (tid == 0) {
        int t = atomicAdd(&g_done, 1);
        if (t == NBLK - 1) {
            #pragma unroll 1
            for (int i = 0; i < NBLK; i++) g_desc[i] = 0;
            g_done = 0;
            __threadfence();
        }
    }
}

// ---------------- scatter (atomic-free) + xh *= dinv[row] scaling ------------
__global__ void k_scatter(const void* __restrict__ ei, const float* __restrict__ ew) {
    int i = blockIdx.x * blockDim.x + threadIdx.x;
    if (i >= NE) return;     // NE == NN*IND/2: same bound covers both jobs
    // job 1: place edge record (src u16 | ew fp16)
    int s, d;
    if (g_is64) {
        const long long* p = (const long long*)ei;
        s = (int)p[i]; d = (int)p[NE + i];
    } else {
        const int* p = (const int*)ei;
        s = p[i]; d = p[NE + i];
    }
    int pos = g_rowptr[d] + (int)g_rank[i];
    g_edge[pos] = (unsigned)s |
                  ((unsigned)__half_as_ushort(__float2half_rn(ew[i])) << 16);
    // job 2: scale x features by dinv[row] (i indexes half2; 32 per row)
    float dn = g_dinv[i >> 5];
    float2 v = __half22float2(((const __half2*)g_xh)[i]);
    ((__half2*)g_xh)[i] = __floats2half2_rn(v.x * dn, v.y * dn);
}

// ---------------- layer-1 aggregation: axh = dinv .* (S @ xs), 64-dim --------
// 2 nodes per warp, 16 lanes per node, uint2 (4 halves) per lane.
__global__ void __launch_bounds__(256) k_aggx() {
    int warpid = (blockIdx.x * 256 + threadIdx.x) >> 5;
    int lane = threadIdx.x & 31;
    int node = warpid * 2 + (lane >> 4);
    int hl = lane & 15;
    if (node >= NN) return;
    float dn = g_dinv[node];
    const uint2* xp = (const uint2*)g_xh;   // 16 uint2 per node row
    uint2 sv = xp[node * 16 + hl];
    float2 a0 = __half22float2(*(__half2*)&sv.x);   // self: dn*xs = dn^2*x
    float2 a1 = __half22float2(*(__half2*)&sv.y);
    int e   = g_rowptr[node];
    int end = g_rowptr[node + 1];
    #pragma unroll 4
    for (; e < end; e++) {
        unsigned rec = __ldg(&g_edge[e]);           // half-warp broadcast
        int src  = rec & 0xFFFFu;
        float w  = __half2float(__ushort_as_half((unsigned short)(rec >> 16)));
        uint2 hv = xp[src * 16 + hl];               // 128B per half-warp
        float2 f0 = __half22float2(*(__half2*)&hv.x);
        float2 f1 = __half22float2(*(__half2*)&hv.y);
        a0.x += f0.x * w; a0.y += f0.y * w;
        a1.x += f1.x * w; a1.y += f1.y * w;
    }
    __half2 h0 = __floats2half2_rn(a0.x * dn, a0.y * dn);
    __half2 h1 = __floats2half2_rn(a1.x * dn, a1.y * dn);
    uint2 pk;
    pk.x = *(unsigned*)&h0;
    pk.y = *(unsigned*)&h1;
    ((uint2*)g_axh)[node * 16 + hl] = pk;
}

// ---------------- fused double GEMM: h2h = dinv .* ((relu(ax@W1+b1)) @ W2) ----
__global__ void __launch_bounds__(256) k_gemmf(const float* __restrict__ bias) {
    constexpr int LDU = 136;           // halves (128+8 pad)
    constexpr int KC  = 32;
    __shared__ __half U[128 * LDU];    // 34.8 KB: stage-1 A, then a1 tile
    __shared__ __half Bs[KC * LDU];    //  8.7 KB: W chunks
    int tid = threadIdx.x;
    int row0 = blockIdx.x * 128;
    int warp = tid >> 5, lane = tid & 31;
    int wm = (warp & 3) * 32;
    int wn = (warp >> 2) * 64;
    float acc[2][8][4];

    #pragma unroll
    for (int mi = 0; mi < 2; mi++)
        #pragma unroll
        for (int nj = 0; nj < 8; nj++)
            #pragma unroll
            for (int q = 0; q < 4; q++) acc[mi][nj][q] = 0.f;

    for (int i = tid; i < 128 * IND / 8; i += 256) {
        int r = i >> 3, c = (i & 7) * 8;
        uint4 v = make_uint4(0u, 0u, 0u, 0u);
        if (row0 + r < NN)
            v = ((const uint4*)g_axh)[(row0 + r) * (IND / 8) + c / 8];
        *(uint4*)&U[r * LDU + c] = v;
    }
    #pragma unroll 1
    for (int kc = 0; kc < IND; kc += KC) {
        __syncthreads();
        for (int i = tid; i < KC * 128 / 8; i += 256) {
            int r = i >> 4, c = (i & 15) * 8;
            *(uint4*)&Bs[r * LDU + c] = ((const uint4*)g_w1h)[((kc + r) * 128 + c) / 8];
        }
        __syncthreads();
        #pragma unroll
        for (int k = 0; k < KC; k += 16) {
            uint32_t a[2][4], b[4][4];
            #pragma unroll
            for (int mi = 0; mi < 2; mi++) {
                uint32_t addr = (uint32_t)__cvta_generic_to_shared(
                    &U[(wm + mi * 16 + (lane & 15)) * LDU + kc + k + 8 * (lane >> 4)]);
                asm volatile("ldmatrix.sync.aligned.m8n8.x4.shared.b16 {%0,%1,%2,%3}, [%4];"
                             : "=r"(a[mi][0]), "=r"(a[mi][1]), "=r"(a[mi][2]), "=r"(a[mi][3])
                             : "r"(addr));
            }
            #pragma unroll
            for (int ni = 0; ni < 4; ni++) {
                uint32_t addr = (uint32_t)__cvta_generic_to_shared(
                    &Bs[(k + (lane & 15)) * LDU + wn + ni * 16 + 8 * (lane >> 4)]);
                asm volatile("ldmatrix.sync.aligned.m8n8.x4.trans.shared.b16 {%0,%1,%2,%3}, [%4];"
                             : "=r"(b[ni][0]), "=r"(b[ni][1]), "=r"(b[ni][2]), "=r"(b[ni][3])
                             : "r"(addr));
            }
            #pragma unroll
            for (int mi = 0; mi < 2; mi++)
                #pragma unroll
                for (int nj = 0; nj < 8; nj++) {
                    uint32_t b0 = b[nj >> 1][(nj & 1) * 2 + 0];
                    uint32_t b1 = b[nj >> 1][(nj & 1) * 2 + 1];
                    asm volatile(
                        "mma.sync.aligned.m16n8k16.row.col.f32.f16.f16.f32 "
                        "{%0,%1,%2,%3}, {%4,%5,%6,%7}, {%8,%9}, {%0,%1,%2,%3};"
                        : "+f"(acc[mi][nj][0]), "+f"(acc[mi][nj][1]),
                          "+f"(acc[mi][nj][2]), "+f"(acc[mi][nj][3])
                        : "r"(a[mi][0]), "r"(a[mi][1]), "r"(a[mi][2]), "r"(a[mi][3]),
                          "r"(b0), "r"(b1));
                }
        }
    }
    __syncthreads();
    #pragma unroll
    for (int mi = 0; mi < 2; mi++)
        #pragma unroll
        for (int nj = 0; nj < 8; nj++) {
            int col = wn + nj * 8 + 2 * (lane & 3);
            float bx = bias[col], by = bias[col + 1];
            #pragma unroll
            for (int h = 0; h < 2; h++) {
                int r = wm + mi * 16 + (lane >> 2) + h * 8;
                float v0 = fmaxf(acc[mi][nj][2 * h + 0] + bx, 0.f);
                float v1 = fmaxf(acc[mi][nj][2 * h + 1] + by, 0.f);
                *(__half2*)&U[r * LDU + col] = __floats2half2_rn(v0, v1);
                acc[mi][nj][2 * h + 0] = 0.f;
                acc[mi][nj][2 * h + 1] = 0.f;
            }
        }
    #pragma unroll 1
    for (int kc = 0; kc < HID; kc += KC) {
        __syncthreads();
        for (int i = tid; i < KC * 128 / 8; i += 256) {
            int r = i >> 4, c = (i & 15) * 8;
            *(uint4*)&Bs[r * LDU + c] = ((const uint4*)g_w2h)[((kc + r) * 128 + c) / 8];
        }
        __syncthreads();
        #pragma unroll
        for (int k = 0; k < KC; k += 16) {
            uint32_t a[2][4], b[4][4];
            #pragma unroll
            for (int mi = 0; mi < 2; mi++) {
                uint32_t addr = (uint32_t)__cvta_generic_to_shared(
                    &U[(wm + mi * 16 + (lane & 15)) * LDU + kc + k + 8 * (lane >> 4)]);
                asm volatile("ldmatrix.sync.aligned.m8n8.x4.shared.b16 {%0,%1,%2,%3}, [%4];"
                             : "=r"(a[mi][0]), "=r"(a[mi][1]), "=r"(a[mi][2]), "=r"(a[mi][3])
                             : "r"(addr));
            }
            #pragma unroll
            for (int ni = 0; ni < 4; ni++) {
                uint32_t addr = (uint32_t)__cvta_generic_to_shared(
                    &Bs[(k + (lane & 15)) * LDU + wn + ni * 16 + 8 * (lane >> 4)]);
                asm volatile("ldmatrix.sync.aligned.m8n8.x4.trans.shared.b16 {%0,%1,%2,%3}, [%4];"
                             : "=r"(b[ni][0]), "=r"(b[ni][1]), "=r"(b[ni][2]), "=r"(b[ni][3])
                             : "r"(addr));
            }
            #pragma unroll
            for (int mi = 0; mi < 2; mi++)
                #pragma unroll
                for (int nj = 0; nj < 8; nj++) {
                    uint32_t b0 = b[nj >> 1][(nj & 1) * 2 + 0];
                    uint32_t b1 = b[nj >> 1][(nj & 1) * 2 + 1];
                    asm volatile(
                        "mma.sync.aligned.m16n8k16.row.col.f32.f16.f16.f32 "
                        "{%0,%1,%2,%3}, {%4,%5,%6,%7}, {%8,%9}, {%0,%1,%2,%3};"
                        : "+f"(acc[mi][nj][0]), "+f"(acc[mi][nj][1]),
                          "+f"(acc[mi][nj][2]), "+f"(acc[mi][nj][3])
                        : "r"(a[mi][0]), "r"(a[mi][1]), "r"(a[mi][2]), "r"(a[mi][3]),
                          "r"(b0), "r"(b1));
                }
        }
    }
    #pragma unroll
    for (int mi = 0; mi < 2; mi++)
        #pragma unroll
        for (int nj = 0; nj < 8; nj++) {
            int col = wn + nj * 8 + 2 * (lane & 3);
            #pragma unroll
            for (int h = 0; h < 2; h++) {
                int r = row0 + wm + mi * 16 + (lane >> 2) + h * 8;
                if (r < NN) {
                    float dn = g_dinv[r];
                    float v0 = acc[mi][nj][2 * h + 0] * dn;
                    float v1 = acc[mi][nj][2 * h + 1] * dn;
                    ((__half2*)g_h2h)[(r * 128 + col) >> 1] = __floats2half2_rn(v0, v1);
                }
            }
        }
}

// ---------------- layer-2 aggregation: a2h = fp16(relu(S @ h2 + b2)) ---------
__global__ void __launch_bounds__(256) k_agg128(const float* __restrict__ bias) {
    int node = (blockIdx.x * 256 + threadIdx.x) >> 5;
    int lane = threadIdx.x & 31;
    if (node >= NN) return;
    float dn = g_dinv[node];
    uint2 sv = ((const uint2*)g_h2h)[node * 32 + lane];
    float2 s0 = __half22float2(*(__half2*)&sv.x);
    float2 s1 = __half22float2(*(__half2*)&sv.y);
    float4 acc = make_float4(s0.x, s0.y, s1.x, s1.y);
    int e   = g_rowptr[node];
    int end = g_rowptr[node + 1];
    #pragma unroll 4
    for (; e < end; e++) {
        unsigned rec = __ldg(&g_edge[e]);
        int src  = rec & 0xFFFFu;
        float w  = __half2float(__ushort_as_half((unsigned short)(rec >> 16)));
        uint2 hv = ((const uint2*)g_h2h)[src * 32 + lane];
        float2 f0 = __half22float2(*(__half2*)&hv.x);
        float2 f1 = __half22float2(*(__half2*)&hv.y);
        acc.x += f0.x * w; acc.y += f0.y * w;
        acc.z += f1.x * w; acc.w += f1.y * w;
    }
    float4 b = ((const float4*)bias)[lane];
    acc.x = fmaxf(acc.x * dn + b.x, 0.f);
    acc.y = fmaxf(acc.y * dn + b.y, 0.f);
    acc.z = fmaxf(acc.z * dn + b.z, 0.f);
    acc.w = fmaxf(acc.w * dn + b.w, 0.f);
    uint2 pk;
    __half2 h0 = __floats2half2_rn(acc.x, acc.y);
    __half2 h1 = __floats2half2_rn(acc.z, acc.w);
    pk.x = *(unsigned*)&h0;
    pk.y = *(unsigned*)&h1;
    ((uint2*)g_a2h)[node * 32 + lane] = pk;
}

// ---------------- fused pool (sorted batch -> contiguous ranges) + MLP head --
__global__ void __launch_bounds__(128) k_poolmlp(const float* __restrict__ Wm1,
                                                 const float* __restrict__ bm1,
                                                 const float* __restrict__ Wm2,
                                                 const float* __restrict__ bm2,
                                                 float* __restrict__ out) {
    int g = blockIdx.x;
    int tid = threadIdx.x;
    __shared__ float ps[HID];
    __shared__ float zs[HID];
    int n0 = g_gptr[g], n1 = g_gptr[g + 1];
    float acc = 0.f;
    for (int n = n0; n < n1; n++)
        acc += __half2float(g_a2h[n * HID + tid]);
    ps[tid] = acc;
    __syncthreads();
    float z = bm1[tid];
    #pragma unroll 8
    for (int k = 0; k < HID; k++) z += ps[k] * Wm1[k * HID + tid];
    zs[tid] = fmaxf(z, 0.f);
    __syncthreads();
    if (tid < OUTD) {
        float a = bm2[tid];
        #pragma unroll 8
        for (int k = 0; k < HID; k++) a += zs[k] * Wm2[k * OUTD + tid];
        out[g * OUTD + tid] = a;
    }
}

// ---------------- launch ----------------
extern "C" void kernel_launch(void* const* d_in, const int* in_sizes, int n_in,
                              void* d_out, int out_size) {
    const float* x   = (const float*)d_in[0];
    const void*  ei  = d_in[1];
    const void*  bt  = d_in[2];
    const float* ew  = (const float*)d_in[3];
    const float* W1  = (const float*)d_in[4];
    const float* b1  = (const float*)d_in[5];
    const float* W2  = (const float*)d_in[6];
    const float* b2  = (const float*)d_in[7];
    const float* Wm1 = (const float*)d_in[8];
    const float* bm1 = (const float*)d_in[9];
    const float* Wm2 = (const float*)d_in[10];
    const float* bm2 = (const float*)d_in[11];
    float* out = (float*)d_out;

    k_histpre<<<(NE + 255) / 256, 256>>>(ei, bt, ew, x, W1, W2);
    k_scan<<<NBLK, SCAN_B>>>();
    k_scatter<<<(NE + 255) / 256, 256>>>(ei, ew);
    k_aggx<<<(NN / 2 * 32 + 255) / 256, 256>>>();
    k_gemmf<<<(NN + 127) / 128, 256>>>(b1);
    k_agg128<<<(NN * 32 + 255) / 256, 256>>>(b2);
    k_poolmlp<<<NG, 128>>>(Wm1, bm1, Wm2, bm2, out);
}

// round 11
// speedup vs baseline: 1.1050x; 1.0148x over previous
#include <cuda_runtime.h>
#include <cuda_fp16.h>
#include <cstdint>

#define NN   50000
#define NE   1600000
#define NG   512
#define IND  64
#define HID  128
#define OUTD 10
#define SCAN_B 1024
#define NBLK ((NN + SCAN_B - 1) / SCAN_B)   // 49
#define FLAG_AGG (1 << 30)
#define FLAG_INC (2 << 30)
#define VAL_MASK ((1 << 30) - 1)
#define FULL 0xffffffffu

// ---------------- scratch (static __device__, zero-initialized; every kernel
// restores what it consumes so the graph can be replayed indefinitely) --------
__device__ int            g_is64;
__device__ float          g_deg[NN];     // starts 0; scan resets after dinv
__device__ float          g_dinv[NN];
__device__ int            g_count[NN];   // starts 0; scan resets
__device__ int            g_rowptr[NN + 1];
__device__ unsigned short g_rank[NE];    // edge rank within dst bucket
__device__ unsigned       g_edge[NE];    // packed: src u16 | ew fp16 << 16
__device__ int            g_desc[NBLK];  // lookback descriptors; last block resets
__device__ int            g_done;        // ticket counter; last block resets
__device__ int            g_gcount[NG];  // starts 0; scan resets
__device__ int            g_gptr[NG + 1];
__device__ __half         g_xh[NN * IND];   // fp16 x; scaled by dinv[row] in scatter
__device__ __half         g_w1h[IND * HID];
__device__ __half         g_w2h[HID * HID];
__device__ __half         g_axh[NN * IND];  // fp16 dinv.*(S @ xs)
__device__ __half         g_h2h[NN * HID];  // fp16 dinv.*(a1 @ W2)
__device__ __half         g_a2h[NN * HID];  // fp16 relu(S @ h2 + b2)

// ---------------- fused: is64 detect + histograms (+rank) + fp16 conversions -
__global__ void k_histpre(const void* __restrict__ ei, const void* __restrict__ batch,
                          const float* __restrict__ ew, const float* __restrict__ x,
                          const float* __restrict__ W1, const float* __restrict__ W2) {
    __shared__ int s_flag;
    int tid = threadIdx.x;
    if (tid == 0) s_flag = 1;
    __syncthreads();
    if (tid < 128) {
        if (((const unsigned*)ei)[2 * tid + 1] != 0u) s_flag = 0;  // benign race
    }
    __syncthreads();
    int is64 = s_flag;
    if (blockIdx.x == 0 && tid == 0) g_is64 = is64;   // publish for k_scatter

    int i = blockIdx.x * blockDim.x + tid;
    if (i < NE) {
        int d = is64 ? (int)((const long long*)ei)[NE + i] : ((const int*)ei)[NE + i];
        atomicAdd(&g_deg[d], ew[i]);
        g_rank[i] = (unsigned short)atomicAdd(&g_count[d], 1);
    }
    if (i < NN) {
        int b = is64 ? (int)((const long long*)batch)[i] : ((const int*)batch)[i];
        atomicAdd(&g_gcount[b], 1);
    }
    if (i < NN * IND / 2) {
        float2 v = ((const float2*)x)[i];
        ((__half2*)g_xh)[i] = __floats2half2_rn(v.x, v.y);
    }
    if (i < IND * HID / 2) {
        float2 v = ((const float2*)W1)[i];
        ((__half2*)g_w1h)[i] = __floats2half2_rn(v.x, v.y);
    }
    if (i < HID * HID / 2) {
        float2 v = ((const float2*)W2)[i];
        ((__half2*)g_w2h)[i] = __floats2half2_rn(v.x, v.y);
    }
}

// ---------------- single-pass scan: counts->rowptr, dinv, gptr ---------------
__global__ void __launch_bounds__(SCAN_B) k_scan() {
    __shared__ int ws[32];
    __shared__ int ws2[16];
    __shared__ int s_excl;
    int tid = threadIdx.x, lane = tid & 31, warp = tid >> 5;
    int b = blockIdx.x;
    int idx = b * SCAN_B + tid;
    int v = 0;
    if (idx < NN) {
        v = g_count[idx];
        g_count[idx] = 0;                           // restore
        g_dinv[idx] = rsqrtf(1.0f + g_deg[idx]);    // self-loop weight 1
        g_deg[idx] = 0.0f;                          // restore
    }
    int xi = v;
    #pragma unroll
    for (int off = 1; off < 32; off <<= 1) {
        int t = __shfl_up_sync(FULL, xi, off);
        if (lane >= off) xi += t;
    }
    if (lane == 31) ws[warp] = xi;
    __syncthreads();
    if (warp == 0) {
        int y = ws[lane];
        #pragma unroll
        for (int off = 1; off < 32; off <<= 1) {
            int t = __shfl_up_sync(FULL, y, off);
            if (lane >= off) y += t;
        }
        ws[lane] = y;
        int total = __shfl_sync(FULL, y, 31);
        if (lane == 0) {
            *((volatile int*)&g_desc[b]) = FLAG_AGG | total;
            __threadfence();
        }
        int excl = 0;
        if (b > 0) {
            int p = b - 1;
            for (;;) {
                int j = p - lane;
                int d;
                do {
                    d = (j >= 0) ? *((volatile int*)&g_desc[j]) : FLAG_INC;
                } while (__any_sync(FULL, d == 0));
                unsigned incmask = __ballot_sync(FULL, (d & FLAG_INC) != 0);
                if (incmask) {
                    int fi = __ffs(incmask) - 1;
                    int c = (lane <= fi) ? (d & VAL_MASK) : 0;
                    #pragma unroll
                    for (int off = 16; off > 0; off >>= 1)
                        c += __shfl_down_sync(FULL, c, off);
                    excl += __shfl_sync(FULL, c, 0);
                    break;
                } else {
                    int c = d & VAL_MASK;
                    #pragma unroll
                    for (int off = 16; off > 0; off >>= 1)
                        c += __shfl_down_sync(FULL, c, off);
                    excl += __shfl_sync(FULL, c, 0);
                    p -= 32;
                }
            }
        }
        if (lane == 0) {
            *((volatile int*)&g_desc[b]) = FLAG_INC | (excl + total);
            __threadfence();
            s_excl = excl;
        }
    }
    __syncthreads();
    int excl = s_excl;
    int incl = xi + (warp ? ws[warp - 1] : 0);
    if (idx < NN) g_rowptr[idx] = excl + incl - v;
    if (b == 0 && tid == 0) g_rowptr[NN] = NE;

    // block 0: gptr scan over NG=512 bins
    int gv = 0;
    if (b == 0 && tid < NG) { gv = g_gcount[tid]; g_gcount[tid] = 0; }
    int x2 = gv;
    #pragma unroll
    for (int off = 1; off < 32; off <<= 1) {
        int t = __shfl_up_sync(FULL, x2, off);
        if (lane >= off) x2 += t;
    }
    if (b == 0 && tid < NG && lane == 31) ws2[warp] = x2;
    __syncthreads();
    if (b == 0 && warp == 0 && lane < 16) {
        int y = ws2[lane];
        #pragma unroll
        for (int off = 1; off < 16; off <<= 1) {
            int t = __shfl_up_sync(0xffffu, y, off);
            if (lane >= off) y += t;
        }
        ws2[lane] = y;
    }
    __syncthreads();
    if (b == 0 && tid < NG)
        g_gptr[tid] = x2 + (warp ? ws2[warp - 1] : 0) - gv;
    if (b == 0 && tid == 0) g_gptr[NG] = NN;

    __syncthreads();
    if (tid == 0) {
        int t = atomicAdd(&g_done, 1);
        if (t == NBLK - 1) {
            #pragma unroll 1
            for (int i = 0; i < NBLK; i++) g_desc[i] = 0;
            g_done = 0;
            __threadfence();
        }
    }
}

// ---------------- scatter (atomic-free) + xh *= dinv[row] scaling ------------
__global__ void k_scatter(const void* __restrict__ ei, const float* __restrict__ ew) {
    int i = blockIdx.x * blockDim.x + threadIdx.x;
    if (i >= NE) return;     // NE == NN*IND/2: same bound covers both jobs
    // job 1: place edge record (src u16 | ew fp16)
    int s, d;
    if (g_is64) {
        const long long* p = (const long long*)ei;
        s = (int)p[i]; d = (int)p[NE + i];
    } else {
        const int* p = (const int*)ei;
        s = p[i]; d = p[NE + i];
    }
    int pos = g_rowptr[d] + (int)g_rank[i];
    g_edge[pos] = (unsigned)s |
                  ((unsigned)__half_as_ushort(__float2half_rn(ew[i])) << 16);
    // job 2: scale x features by dinv[row] (i indexes half2; 32 per row)
    float dn = g_dinv[i >> 5];
    float2 v = __half22float2(((const __half2*)g_xh)[i]);
    ((__half2*)g_xh)[i] = __floats2half2_rn(v.x * dn, v.y * dn);
}

// ---------------- layer-1 aggregation: axh = dinv .* (S @ xs), 64-dim --------
// 4 nodes per warp, 8 lanes per node, uint4 (8 halves) per lane.
__global__ void __launch_bounds__(256) k_aggx() {
    int warpid = (blockIdx.x * 256 + threadIdx.x) >> 5;
    int lane = threadIdx.x & 31;
    int node = warpid * 4 + (lane >> 3);
    int ql = lane & 7;                      // lane within 8-lane group
    if (node >= NN) return;
    float dn = g_dinv[node];
    const uint4* xp = (const uint4*)g_xh;   // 8 uint4 per node row (64 halves)
    uint4 sv = xp[node * 8 + ql];
    float2 a0 = __half22float2(*(__half2*)&sv.x);   // self: dn*xs = dn^2*x
    float2 a1 = __half22float2(*(__half2*)&sv.y);
    float2 a2 = __half22float2(*(__half2*)&sv.z);
    float2 a3 = __half22float2(*(__half2*)&sv.w);
    int e   = g_rowptr[node];
    int end = g_rowptr[node + 1];
    #pragma unroll 4
    for (; e < end; e++) {
        unsigned rec = __ldg(&g_edge[e]);           // 8-lane broadcast
        int src  = rec & 0xFFFFu;
        float w  = __half2float(__ushort_as_half((unsigned short)(rec >> 16)));
        uint4 hv = xp[src * 8 + ql];                // 128B per 8-lane group
        float2 f0 = __half22float2(*(__half2*)&hv.x);
        float2 f1 = __half22float2(*(__half2*)&hv.y);
        float2 f2 = __half22float2(*(__half2*)&hv.z);
        float2 f3 = __half22float2(*(__half2*)&hv.w);
        a0.x += f0.x * w; a0.y += f0.y * w;
        a1.x += f1.x * w; a1.y += f1.y * w;
        a2.x += f2.x * w; a2.y += f2.y * w;
        a3.x += f3.x * w; a3.y += f3.y * w;
    }
    __half2 h0 = __floats2half2_rn(a0.x * dn, a0.y * dn);
    __half2 h1 = __floats2half2_rn(a1.x * dn, a1.y * dn);
    __half2 h2 = __floats2half2_rn(a2.x * dn, a2.y * dn);
    __half2 h3 = __floats2half2_rn(a3.x * dn, a3.y * dn);
    uint4 pk;
    pk.x = *(unsigned*)&h0;
    pk.y = *(unsigned*)&h1;
    pk.z = *(unsigned*)&h2;
    pk.w = *(unsigned*)&h3;
    ((uint4*)g_axh)[node * 8 + ql] = pk;
}

// ---------------- fused double GEMM: h2h = dinv .* ((relu(ax@W1+b1)) @ W2) ----
__global__ void __launch_bounds__(256) k_gemmf(const float* __restrict__ bias) {
    constexpr int LDU = 136;           // halves (128+8 pad)
    constexpr int KC  = 32;
    __shared__ __half U[128 * LDU];    // 34.8 KB: stage-1 A, then a1 tile
    __shared__ __half Bs[KC * LDU];    //  8.7 KB: W chunks
    int tid = threadIdx.x;
    int row0 = blockIdx.x * 128;
    int warp = tid >> 5, lane = tid & 31;
    int wm = (warp & 3) * 32;
    int wn = (warp >> 2) * 64;
    float acc[2][8][4];

    #pragma unroll
    for (int mi = 0; mi < 2; mi++)
        #pragma unroll
        for (int nj = 0; nj < 8; nj++)
            #pragma unroll
            for (int q = 0; q < 4; q++) acc[mi][nj][q] = 0.f;

    for (int i = tid; i < 128 * IND / 8; i += 256) {
        int r = i >> 3, c = (i & 7) * 8;
        uint4 v = make_uint4(0u, 0u, 0u, 0u);
        if (row0 + r < NN)
            v = ((const uint4*)g_axh)[(row0 + r) * (IND / 8) + c / 8];
        *(uint4*)&U[r * LDU + c] = v;
    }
    #pragma unroll 1
    for (int kc = 0; kc < IND; kc += KC) {
        __syncthreads();
        for (int i = tid; i < KC * 128 / 8; i += 256) {
            int r = i >> 4, c = (i & 15) * 8;
            *(uint4*)&Bs[r * LDU + c] = ((const uint4*)g_w1h)[((kc + r) * 128 + c) / 8];
        }
        __syncthreads();
        #pragma unroll
        for (int k = 0; k < KC; k += 16) {
            uint32_t a[2][4], b[4][4];
            #pragma unroll
            for (int mi = 0; mi < 2; mi++) {
                uint32_t addr = (uint32_t)__cvta_generic_to_shared(
                    &U[(wm + mi * 16 + (lane & 15)) * LDU + kc + k + 8 * (lane >> 4)]);
                asm volatile("ldmatrix.sync.aligned.m8n8.x4.shared.b16 {%0,%1,%2,%3}, [%4];"
                             : "=r"(a[mi][0]), "=r"(a[mi][1]), "=r"(a[mi][2]), "=r"(a[mi][3])
                             : "r"(addr));
            }
            #pragma unroll
            for (int ni = 0; ni < 4; ni++) {
                uint32_t addr = (uint32_t)__cvta_generic_to_shared(
                    &Bs[(k + (lane & 15)) * LDU + wn + ni * 16 + 8 * (lane >> 4)]);
                asm volatile("ldmatrix.sync.aligned.m8n8.x4.trans.shared.b16 {%0,%1,%2,%3}, [%4];"
                             : "=r"(b[ni][0]), "=r"(b[ni][1]), "=r"(b[ni][2]), "=r"(b[ni][3])
                             : "r"(addr));
            }
            #pragma unroll
            for (int mi = 0; mi < 2; mi++)
                #pragma unroll
                for (int nj = 0; nj < 8; nj++) {
                    uint32_t b0 = b[nj >> 1][(nj & 1) * 2 + 0];
                    uint32_t b1 = b[nj >> 1][(nj & 1) * 2 + 1];
                    asm volatile(
                        "mma.sync.aligned.m16n8k16.row.col.f32.f16.f16.f32 "
                        "{%0,%1,%2,%3}, {%4,%5,%6,%7}, {%8,%9}, {%0,%1,%2,%3};"
                        : "+f"(acc[mi][nj][0]), "+f"(acc[mi][nj][1]),
                          "+f"(acc[mi][nj][2]), "+f"(acc[mi][nj][3])
                        : "r"(a[mi][0]), "r"(a[mi][1]), "r"(a[mi][2]), "r"(a[mi][3]),
                          "r"(b0), "r"(b1));
                }
        }
    }
    __syncthreads();
    #pragma unroll
    for (int mi = 0; mi < 2; mi++)
        #pragma unroll
        for (int nj = 0; nj < 8; nj++) {
            int col = wn + nj * 8 + 2 * (lane & 3);
            float bx = bias[col], by = bias[col + 1];
            #pragma unroll
            for (int h = 0; h < 2; h++) {
                int r = wm + mi * 16 + (lane >> 2) + h * 8;
                float v0 = fmaxf(acc[mi][nj][2 * h + 0] + bx, 0.f);
                float v1 = fmaxf(acc[mi][nj][2 * h + 1] + by, 0.f);
                *(__half2*)&U[r * LDU + col] = __floats2half2_rn(v0, v1);
                acc[mi][nj][2 * h + 0] = 0.f;
                acc[mi][nj][2 * h + 1] = 0.f;
            }
        }
    #pragma unroll 1
    for (int kc = 0; kc < HID; kc += KC) {
        __syncthreads();
        for (int i = tid; i < KC * 128 / 8; i += 256) {
            int r = i >> 4, c = (i & 15) * 8;
            *(uint4*)&Bs[r * LDU + c] = ((const uint4*)g_w2h)[((kc + r) * 128 + c) / 8];
        }
        __syncthreads();
        #pragma unroll
        for (int k = 0; k < KC; k += 16) {
            uint32_t a[2][4], b[4][4];
            #pragma unroll
            for (int mi = 0; mi < 2; mi++) {
                uint32_t addr = (uint32_t)__cvta_generic_to_shared(
                    &U[(wm + mi * 16 + (lane & 15)) * LDU + kc + k + 8 * (lane >> 4)]);
                asm volatile("ldmatrix.sync.aligned.m8n8.x4.shared.b16 {%0,%1,%2,%3}, [%4];"
                             : "=r"(a[mi][0]), "=r"(a[mi][1]), "=r"(a[mi][2]), "=r"(a[mi][3])
                             : "r"(addr));
            }
            #pragma unroll
            for (int ni = 0; ni < 4; ni++) {
                uint32_t addr = (uint32_t)__cvta_generic_to_shared(
                    &Bs[(k + (lane & 15)) * LDU + wn + ni * 16 + 8 * (lane >> 4)]);
                asm volatile("ldmatrix.sync.aligned.m8n8.x4.trans.shared.b16 {%0,%1,%2,%3}, [%4];"
                             : "=r"(b[ni][0]), "=r"(b[ni][1]), "=r"(b[ni][2]), "=r"(b[ni][3])
                             : "r"(addr));
            }
            #pragma unroll
            for (int mi = 0; mi < 2; mi++)
                #pragma unroll
                for (int nj = 0; nj < 8; nj++) {
                    uint32_t b0 = b[nj >> 1][(nj & 1) * 2 + 0];
                    uint32_t b1 = b[nj >> 1][(nj & 1) * 2 + 1];
                    asm volatile(
                        "mma.sync.aligned.m16n8k16.row.col.f32.f16.f16.f32 "
                        "{%0,%1,%2,%3}, {%4,%5,%6,%7}, {%8,%9}, {%0,%1,%2,%3};"
                        : "+f"(acc[mi][nj][0]), "+f"(acc[mi][nj][1]),
                          "+f"(acc[mi][nj][2]), "+f"(acc[mi][nj][3])
                        : "r"(a[mi][0]), "r"(a[mi][1]), "r"(a[mi][2]), "r"(a[mi][3]),
                          "r"(b0), "r"(b1));
                }
        }
    }
    #pragma unroll
    for (int mi = 0; mi < 2; mi++)
        #pragma unroll
        for (int nj = 0; nj < 8; nj++) {
            int col = wn + nj * 8 + 2 * (lane & 3);
            #pragma unroll
            for (int h = 0; h < 2; h++) {
                int r = row0 + wm + mi * 16 + (lane >> 2) + h * 8;
                if (r < NN) {
                    float dn = g_dinv[r];
                    float v0 = acc[mi][nj][2 * h + 0] * dn;
                    float v1 = acc[mi][nj][2 * h + 1] * dn;
                    ((__half2*)g_h2h)[(r * 128 + col) >> 1] = __floats2half2_rn(v0, v1);
                }
            }
        }
}

// ---------------- layer-2 aggregation: a2h = fp16(relu(S @ h2 + b2)) ---------
__global__ void __launch_bounds__(256) k_agg128(const float* __restrict__ bias) {
    int node = (blockIdx.x * 256 + threadIdx.x) >> 5;
    int lane = threadIdx.x & 31;
    if (node >= NN) return;
    float dn = g_dinv[node];
    uint2 sv = ((const uint2*)g_h2h)[node * 32 + lane];
    float2 s0 = __half22float2(*(__half2*)&sv.x);
    float2 s1 = __half22float2(*(__half2*)&sv.y);
    float4 acc = make_float4(s0.x, s0.y, s1.x, s1.y);
    int e   = g_rowptr[node];
    int end = g_rowptr[node + 1];
    #pragma unroll 4
    for (; e < end; e++) {
        unsigned rec = __ldg(&g_edge[e]);
        int src  = rec & 0xFFFFu;
        float w  = __half2float(__ushort_as_half((unsigned short)(rec >> 16)));
        uint2 hv = ((const uint2*)g_h2h)[src * 32 + lane];
        float2 f0 = __half22float2(*(__half2*)&hv.x);
        float2 f1 = __half22float2(*(__half2*)&hv.y);
        acc.x += f0.x * w; acc.y += f0.y * w;
        acc.z += f1.x * w; acc.w += f1.y * w;
    }
    float4 b = ((const float4*)bias)[lane];
    acc.x = fmaxf(acc.x * dn + b.x, 0.f);
    acc.y = fmaxf(acc.y * dn + b.y, 0.f);
    acc.z = fmaxf(acc.z * dn + b.z, 0.f);
    acc.w = fmaxf(acc.w * dn + b.w, 0.f);
    uint2 pk;
    __half2 h0 = __floats2half2_rn(acc.x, acc.y);
    __half2 h1 = __floats2half2_rn(acc.z, acc.w);
    pk.x = *(unsigned*)&h0;
    pk.y = *(unsigned*)&h1;
    ((uint2*)g_a2h)[node * 32 + lane] = pk;
}

// ---------------- fused pool (sorted batch -> contiguous ranges) + MLP head --
__global__ void __launch_bounds__(128) k_poolmlp(const float* __restrict__ Wm1,
                                                 const float* __restrict__ bm1,
                                                 const float* __restrict__ Wm2,
                                                 const float* __restrict__ bm2,
                                                 float* __restrict__ out) {
    int g = blockIdx.x;
    int tid = threadIdx.x;
    __shared__ float ps[HID];
    __shared__ float zs[HID];
    int n0 = g_gptr[g], n1 = g_gptr[g + 1];
    float acc = 0.f;
    for (int n = n0; n < n1; n++)
        acc += __half2float(g_a2h[n * HID + tid]);
    ps[tid] = acc;
    __syncthreads();
    float z = bm1[tid];
    #pragma unroll 8
    for (int k = 0; k < HID; k++) z += ps[k] * Wm1[k * HID + tid];
    zs[tid] = fmaxf(z, 0.f);
    __syncthreads();
    if (tid < OUTD) {
        float a = bm2[tid];
        #pragma unroll 8
        for (int k = 0; k < HID; k++) a += zs[k] * Wm2[k * OUTD + tid];
        out[g * OUTD + tid] = a;
    }
}

// ---------------- launch ----------------
extern "C" void kernel_launch(void* const* d_in, const int* in_sizes, int n_in,
                              void* d_out, int out_size) {
    const float* x   = (const float*)d_in[0];
    const void*  ei  = d_in[1];
    const void*  bt  = d_in[2];
    const float* ew  = (const float*)d_in[3];
    const float* W1  = (const float*)d_in[4];
    const float* b1  = (const float*)d_in[5];
    const float* W2  = (const float*)d_in[6];
    const float* b2  = (const float*)d_in[7];
    const float* Wm1 = (const float*)d_in[8];
    const float* bm1 = (const float*)d_in[9];
    const float* Wm2 = (const float*)d_in[10];
    const float* bm2 = (const float*)d_in[11];
    float* out = (float*)d_out;

    k_histpre<<<(NE + 255) / 256, 256>>>(ei, bt, ew, x, W1, W2);
    k_scan<<<NBLK, SCAN_B>>>();
    k_scatter<<<(NE + 255) / 256, 256>>>(ei, ew);
    k_aggx<<<(NN / 4 * 32 + 255) / 256, 256>>>();
    k_gemmf<<<(NN + 127) / 128, 256>>>(b1);
    k_agg128<<<(NN * 32 + 255) / 256, 256>>>(b2);
    k_poolmlp<<<NG, 128>>>(Wm1, bm1, Wm2, bm2, out);
}

// round 12
// speedup vs baseline: 1.2166x; 1.1010x over previous
#include <cuda_runtime.h>
#include <cuda_fp16.h>
#include <cstdint>

#define NN   50000
#define NE   1600000
#define NG   512
#define IND  64
#define HID  128
#define OUTD 10
#define SCAN_B 1024
#define NBLK ((NN + SCAN_B - 1) / SCAN_B)   // 49
#define FLAG_AGG (1 << 30)
#define FLAG_INC (2 << 30)
#define VAL_MASK ((1 << 30) - 1)
#define FULL 0xffffffffu

// ---------------- scratch (static __device__, zero-initialized; every kernel
// restores what it consumes so the graph can be replayed indefinitely) --------
__device__ int                g_is64;
__device__ unsigned long long g_degcnt[NN];  // count<<48 | fixed(ew sum, 2^-24); scan resets
__device__ float              g_dinv[NN];
__device__ int                g_rowptr[NN + 1];
__device__ unsigned           g_rankew[NE];  // rank u16 | ew fp16 << 16
__device__ unsigned           g_edge[NE];    // src u16 | ew fp16 << 16
__device__ int                g_desc[NBLK];  // lookback descriptors; last block resets
__device__ int                g_done;        // ticket counter; last block resets
__device__ int                g_gcount[NG];  // starts 0; scan resets
__device__ int                g_gptr[NG + 1];
__device__ __half             g_xh[NN * IND];   // fp16 x; scaled by dinv[row] in scatter
__device__ __half             g_w1h[IND * HID];
__device__ __half             g_w2h[HID * HID];
__device__ __half             g_axh[NN * IND];  // fp16 dinv.*(S @ xs)
__device__ __half             g_h2h[NN * HID];  // fp16 dinv.*(a1 @ W2)
__device__ __half             g_a2h[NN * HID];  // fp16 relu(S @ h2 + b2)

// ---------------- fused: is64 detect + packed histogram + fp16 conversions ---
__global__ void k_histpre(const void* __restrict__ ei, const void* __restrict__ batch,
                          const float* __restrict__ ew, const float* __restrict__ x,
                          const float* __restrict__ W1, const float* __restrict__ W2) {
    __shared__ int s_flag;
    int tid = threadIdx.x;
    if (tid == 0) s_flag = 1;
    __syncthreads();
    if (tid < 128) {
        if (((const unsigned*)ei)[2 * tid + 1] != 0u) s_flag = 0;  // benign race
    }
    __syncthreads();
    int is64 = s_flag;
    if (blockIdx.x == 0 && tid == 0) g_is64 = is64;   // publish for k_scatter

    int i = blockIdx.x * blockDim.x + tid;
    if (i < NE) {
        int d = is64 ? (int)((const long long*)ei)[NE + i] : ((const int*)ei)[NE + i];
        float w = ew[i];
        unsigned long long pk = (1ULL << 48) |
            (unsigned long long)__float2uint_rn(w * 16777216.0f);
        unsigned long long old = atomicAdd(&g_degcnt[d], pk);
        unsigned rank = (unsigned)(old >> 48);           // fits u16 (max deg ~80)
        unsigned ewh  = (unsigned)__half_as_ushort(__float2half_rn(w));
        g_rankew[i] = rank | (ewh << 16);
    }
    if (i < NN) {
        int b = is64 ? (int)((const long long*)batch)[i] : ((const int*)batch)[i];
        atomicAdd(&g_gcount[b], 1);
    }
    if (i < NN * IND / 2) {
        float2 v = ((const float2*)x)[i];
        ((__half2*)g_xh)[i] = __floats2half2_rn(v.x, v.y);
    }
    if (i < IND * HID / 2) {
        float2 v = ((const float2*)W1)[i];
        ((__half2*)g_w1h)[i] = __floats2half2_rn(v.x, v.y);
    }
    if (i < HID * HID / 2) {
        float2 v = ((const float2*)W2)[i];
        ((__half2*)g_w2h)[i] = __floats2half2_rn(v.x, v.y);
    }
}

// ---------------- single-pass scan: degcnt->rowptr+dinv, gptr ----------------
__global__ void __launch_bounds__(SCAN_B) k_scan() {
    __shared__ int ws[32];
    __shared__ int ws2[16];
    __shared__ int s_excl;
    int tid = threadIdx.x, lane = tid & 31, warp = tid >> 5;
    int b = blockIdx.x;
    int idx = b * SCAN_B + tid;
    int v = 0;
    if (idx < NN) {
        unsigned long long dv = g_degcnt[idx];
        g_degcnt[idx] = 0ULL;                       // restore
        v = (int)(dv >> 48);
        float deg = (float)(dv & 0xFFFFFFFFFFFFULL) * (1.0f / 16777216.0f);
        g_dinv[idx] = rsqrtf(1.0f + deg);           // self-loop weight 1
    }
    int xi = v;
    #pragma unroll
    for (int off = 1; off < 32; off <<= 1) {
        int t = __shfl_up_sync(FULL, xi, off);
        if (lane >= off) xi += t;
    }
    if (lane == 31) ws[warp] = xi;
    __syncthreads();
    if (warp == 0) {
        int y = ws[lane];
        #pragma unroll
        for (int off = 1; off < 32; off <<= 1) {
            int t = __shfl_up_sync(FULL, y, off);
            if (lane >= off) y += t;
        }
        ws[lane] = y;
        int total = __shfl_sync(FULL, y, 31);
        if (lane == 0) {
            *((volatile int*)&g_desc[b]) = FLAG_AGG | total;
            __threadfence();
        }
        int excl = 0;
        if (b > 0) {
            int p = b - 1;
            for (;;) {
                int j = p - lane;
                int d;
                do {
                    d = (j >= 0) ? *((volatile int*)&g_desc[j]) : FLAG_INC;
                } while (__any_sync(FULL, d == 0));
                unsigned incmask = __ballot_sync(FULL, (d & FLAG_INC) != 0);
                if (incmask) {
                    int fi = __ffs(incmask) - 1;
                    int c = (lane <= fi) ? (d & VAL_MASK) : 0;
                    #pragma unroll
                    for (int off = 16; off > 0; off >>= 1)
                        c += __shfl_down_sync(FULL, c, off);
                    excl += __shfl_sync(FULL, c, 0);
                    break;
                } else {
                    int c = d & VAL_MASK;
                    #pragma unroll
                    for (int off = 16; off > 0; off >>= 1)
                        c += __shfl_down_sync(FULL, c, off);
                    excl += __shfl_sync(FULL, c, 0);
                    p -= 32;
                }
            }
        }
        if (lane == 0) {
            *((volatile int*)&g_desc[b]) = FLAG_INC | (excl + total);
            __threadfence();
            s_excl = excl;
        }
    }
    __syncthreads();
    int excl = s_excl;
    int incl = xi + (warp ? ws[warp - 1] : 0);
    if (idx < NN) g_rowptr[idx] = excl + incl - v;
    if (b == 0 && tid == 0) g_rowptr[NN] = NE;

    // block 0: gptr scan over NG=512 bins
    int gv = 0;
    if (b == 0 && tid < NG) { gv = g_gcount[tid]; g_gcount[tid] = 0; }
    int x2 = gv;
    #pragma unroll
    for (int off = 1; off < 32; off <<= 1) {
        int t = __shfl_up_sync(FULL, x2, off);
        if (lane >= off) x2 += t;
    }
    if (b == 0 && tid < NG && lane == 31) ws2[warp] = x2;
    __syncthreads();
    if (b == 0 && warp == 0 && lane < 16) {
        int y = ws2[lane];
        #pragma unroll
        for (int off = 1; off < 16; off <<= 1) {
            int t = __shfl_up_sync(0xffffu, y, off);
            if (lane >= off) y += t;
        }
        ws2[lane] = y;
    }
    __syncthreads();
    if (b == 0 && tid < NG)
        g_gptr[tid] = x2 + (warp ? ws2[warp - 1] : 0) - gv;
    if (b == 0 && tid == 0) g_gptr[NG] = NN;

    __syncthreads();
    if (tid == 0) {
        int t = atomicAdd(&g_done, 1);
        if (t == NBLK - 1) {
            #pragma unroll 1
            for (int i = 0; i < NBLK; i++) g_desc[i] = 0;
            g_done = 0;
            __threadfence();
        }
    }
}

// ---------------- scatter (atomic-free) + xh *= dinv[row] scaling ------------
__global__ void k_scatter(const void* __restrict__ ei) {
    int i = blockIdx.x * blockDim.x + threadIdx.x;
    if (i >= NE) return;     // NE == NN*IND/2: same bound covers both jobs
    // job 1: place edge record (src u16 | ew fp16)
    int s, d;
    if (g_is64) {
        const long long* p = (const long long*)ei;
        s = (int)p[i]; d = (int)p[NE + i];
    } else {
        const int* p = (const int*)ei;
        s = p[i]; d = p[NE + i];
    }
    unsigned re = g_rankew[i];
    int pos = g_rowptr[d] + (int)(re & 0xFFFFu);
    g_edge[pos] = (unsigned)s | (re & 0xFFFF0000u);
    // job 2: scale x features by dinv[row] (i indexes half2; 32 per row)
    float dn = g_dinv[i >> 5];
    float2 v = __half22float2(((const __half2*)g_xh)[i]);
    ((__half2*)g_xh)[i] = __floats2half2_rn(v.x * dn, v.y * dn);
}

// ---------------- layer-1 aggregation: axh = dinv .* (S @ xs), 64-dim --------
// 4 nodes per warp, 8 lanes per node, uint4 per lane; 4-edge batches for MLP.
__global__ void __launch_bounds__(256) k_aggx() {
    int warpid = (blockIdx.x * 256 + threadIdx.x) >> 5;
    int lane = threadIdx.x & 31;
    int node = warpid * 4 + (lane >> 3);
    int ql = lane & 7;                      // lane within 8-lane group
    if (node >= NN) return;
    float dn = g_dinv[node];
    const uint4* xp = (const uint4*)g_xh;   // 8 uint4 per node row (64 halves)
    uint4 sv = xp[node * 8 + ql];
    float2 a0 = __half22float2(*(__half2*)&sv.x);   // self: dn*xs = dn^2*x
    float2 a1 = __half22float2(*(__half2*)&sv.y);
    float2 a2 = __half22float2(*(__half2*)&sv.z);
    float2 a3 = __half22float2(*(__half2*)&sv.w);
    int e   = g_rowptr[node];
    int end = g_rowptr[node + 1];
    int e4  = e + ((end - e) & ~3);
    for (; e < e4; e += 4) {
        // 4 records up front, then 4 independent gathers (MLP)
        unsigned r0 = __ldg(&g_edge[e + 0]);
        unsigned r1 = __ldg(&g_edge[e + 1]);
        unsigned r2 = __ldg(&g_edge[e + 2]);
        unsigned r3 = __ldg(&g_edge[e + 3]);
        uint4 v0 = xp[(r0 & 0xFFFFu) * 8 + ql];
        uint4 v1 = xp[(r1 & 0xFFFFu) * 8 + ql];
        uint4 v2 = xp[(r2 & 0xFFFFu) * 8 + ql];
        uint4 v3 = xp[(r3 & 0xFFFFu) * 8 + ql];
        float w0 = __half2float(__ushort_as_half((unsigned short)(r0 >> 16)));
        float w1 = __half2float(__ushort_as_half((unsigned short)(r1 >> 16)));
        float w2 = __half2float(__ushort_as_half((unsigned short)(r2 >> 16)));
        float w3 = __half2float(__ushort_as_half((unsigned short)(r3 >> 16)));
        #define ACC(V, W) { \
            float2 f0 = __half22float2(*(__half2*)&(V).x); \
            float2 f1 = __half22float2(*(__half2*)&(V).y); \
            float2 f2 = __half22float2(*(__half2*)&(V).z); \
            float2 f3 = __half22float2(*(__half2*)&(V).w); \
            a0.x += f0.x * (W); a0.y += f0.y * (W); \
            a1.x += f1.x * (W); a1.y += f1.y * (W); \
            a2.x += f2.x * (W); a2.y += f2.y * (W); \
            a3.x += f3.x * (W); a3.y += f3.y * (W); }
        ACC(v0, w0) ACC(v1, w1) ACC(v2, w2) ACC(v3, w3)
    }
    for (; e < end; e++) {
        unsigned rec = __ldg(&g_edge[e]);
        float w = __half2float(__ushort_as_half((unsigned short)(rec >> 16)));
        uint4 hv = xp[(rec & 0xFFFFu) * 8 + ql];
        ACC(hv, w)
        #undef ACC
    }
    __half2 h0 = __floats2half2_rn(a0.x * dn, a0.y * dn);
    __half2 h1 = __floats2half2_rn(a1.x * dn, a1.y * dn);
    __half2 h2 = __floats2half2_rn(a2.x * dn, a2.y * dn);
    __half2 h3 = __floats2half2_rn(a3.x * dn, a3.y * dn);
    uint4 pk;
    pk.x = *(unsigned*)&h0;
    pk.y = *(unsigned*)&h1;
    pk.z = *(unsigned*)&h2;
    pk.w = *(unsigned*)&h3;
    ((uint4*)g_axh)[node * 8 + ql] = pk;
}

// ---------------- fused double GEMM: h2h = dinv .* ((relu(ax@W1+b1)) @ W2) ----
__global__ void __launch_bounds__(256) k_gemmf(const float* __restrict__ bias) {
    constexpr int LDU = 136;           // halves (128+8 pad)
    constexpr int KC  = 32;
    __shared__ __half U[128 * LDU];    // 34.8 KB: stage-1 A, then a1 tile
    __shared__ __half Bs[KC * LDU];    //  8.7 KB: W chunks
    int tid = threadIdx.x;
    int row0 = blockIdx.x * 128;
    int warp = tid >> 5, lane = tid & 31;
    int wm = (warp & 3) * 32;
    int wn = (warp >> 2) * 64;
    float acc[2][8][4];

    #pragma unroll
    for (int mi = 0; mi < 2; mi++)
        #pragma unroll
        for (int nj = 0; nj < 8; nj++)
            #pragma unroll
            for (int q = 0; q < 4; q++) acc[mi][nj][q] = 0.f;

    for (int i = tid; i < 128 * IND / 8; i += 256) {
        int r = i >> 3, c = (i & 7) * 8;
        uint4 v = make_uint4(0u, 0u, 0u, 0u);
        if (row0 + r < NN)
            v = ((const uint4*)g_axh)[(row0 + r) * (IND / 8) + c / 8];
        *(uint4*)&U[r * LDU + c] = v;
    }
    #pragma unroll 1
    for (int kc = 0; kc < IND; kc += KC) {
        __syncthreads();
        for (int i = tid; i < KC * 128 / 8; i += 256) {
            int r = i >> 4, c = (i & 15) * 8;
            *(uint4*)&Bs[r * LDU + c] = ((const uint4*)g_w1h)[((kc + r) * 128 + c) / 8];
        }
        __syncthreads();
        #pragma unroll
        for (int k = 0; k < KC; k += 16) {
            uint32_t a[2][4], b[4][4];
            #pragma unroll
            for (int mi = 0; mi < 2; mi++) {
                uint32_t addr = (uint32_t)__cvta_generic_to_shared(
                    &U[(wm + mi * 16 + (lane & 15)) * LDU + kc + k + 8 * (lane >> 4)]);
                asm volatile("ldmatrix.sync.aligned.m8n8.x4.shared.b16 {%0,%1,%2,%3}, [%4];"
                             : "=r"(a[mi][0]), "=r"(a[mi][1]), "=r"(a[mi][2]), "=r"(a[mi][3])
                             : "r"(addr));
            }
            #pragma unroll
            for (int ni = 0; ni < 4; ni++) {
                uint32_t addr = (uint32_t)__cvta_generic_to_shared(
                    &Bs[(k + (lane & 15)) * LDU + wn + ni * 16 + 8 * (lane >> 4)]);
                asm volatile("ldmatrix.sync.aligned.m8n8.x4.trans.shared.b16 {%0,%1,%2,%3}, [%4];"
                             : "=r"(b[ni][0]), "=r"(b[ni][1]), "=r"(b[ni][2]), "=r"(b[ni][3])
                             : "r"(addr));
            }
            #pragma unroll
            for (int mi = 0; mi < 2; mi++)
                #pragma unroll
                for (int nj = 0; nj < 8; nj++) {
                    uint32_t b0 = b[nj >> 1][(nj & 1) * 2 + 0];
                    uint32_t b1 = b[nj >> 1][(nj & 1) * 2 + 1];
                    asm volatile(
                        "mma.sync.aligned.m16n8k16.row.col.f32.f16.f16.f32 "
                        "{%0,%1,%2,%3}, {%4,%5,%6,%7}, {%8,%9}, {%0,%1,%2,%3};"
                        : "+f"(acc[mi][nj][0]), "+f"(acc[mi][nj][1]),
                          "+f"(acc[mi][nj][2]), "+f"(acc[mi][nj][3])
                        : "r"(a[mi][0]), "r"(a[mi][1]), "r"(a[mi][2]), "r"(a[mi][3]),
                          "r"(b0), "r"(b1));
                }
        }
    }
    __syncthreads();
    #pragma unroll
    for (int mi = 0; mi < 2; mi++)
        #pragma unroll
        for (int nj = 0; nj < 8; nj++) {
            int col = wn + nj * 8 + 2 * (lane & 3);
            float bx = bias[col], by = bias[col + 1];
            #pragma unroll
            for (int h = 0; h < 2; h++) {
                int r = wm + mi * 16 + (lane >> 2) + h * 8;
                float v0 = fmaxf(acc[mi][nj][2 * h + 0] + bx, 0.f);
                float v1 = fmaxf(acc[mi][nj][2 * h + 1] + by, 0.f);
                *(__half2*)&U[r * LDU + col] = __floats2half2_rn(v0, v1);
                acc[mi][nj][2 * h + 0] = 0.f;
                acc[mi][nj][2 * h + 1] = 0.f;
            }
        }
    #pragma unroll 1
    for (int kc = 0; kc < HID; kc += KC) {
        __syncthreads();
        for (int i = tid; i < KC * 128 / 8; i += 256) {
            int r = i >> 4, c = (i & 15) * 8;
            *(uint4*)&Bs[r * LDU + c] = ((const uint4*)g_w2h)[((kc + r) * 128 + c) / 8];
        }
        __syncthreads();
        #pragma unroll
        for (int k = 0; k < KC; k += 16) {
            uint32_t a[2][4], b[4][4];
            #pragma unroll
            for (int mi = 0; mi < 2; mi++) {
                uint32_t addr = (uint32_t)__cvta_generic_to_shared(
                    &U[(wm + mi * 16 + (lane & 15)) * LDU + kc + k + 8 * (lane >> 4)]);
                asm volatile("ldmatrix.sync.aligned.m8n8.x4.shared.b16 {%0,%1,%2,%3}, [%4];"
                             : "=r"(a[mi][0]), "=r"(a[mi][1]), "=r"(a[mi][2]), "=r"(a[mi][3])
                             : "r"(addr));
            }
            #pragma unroll
            for (int ni = 0; ni < 4; ni++) {
                uint32_t addr = (uint32_t)__cvta_generic_to_shared(
                    &Bs[(k + (lane & 15)) * LDU + wn + ni * 16 + 8 * (lane >> 4)]);
                asm volatile("ldmatrix.sync.aligned.m8n8.x4.trans.shared.b16 {%0,%1,%2,%3}, [%4];"
                             : "=r"(b[ni][0]), "=r"(b[ni][1]), "=r"(b[ni][2]), "=r"(b[ni][3])
                             : "r"(addr));
            }
            #pragma unroll
            for (int mi = 0; mi < 2; mi++)
                #pragma unroll
                for (int nj = 0; nj < 8; nj++) {
                    uint32_t b0 = b[nj >> 1][(nj & 1) * 2 + 0];
                    uint32_t b1 = b[nj >> 1][(nj & 1) * 2 + 1];
                    asm volatile(
                        "mma.sync.aligned.m16n8k16.row.col.f32.f16.f16.f32 "
                        "{%0,%1,%2,%3}, {%4,%5,%6,%7}, {%8,%9}, {%0,%1,%2,%3};"
                        : "+f"(acc[mi][nj][0]), "+f"(acc[mi][nj][1]),
                          "+f"(acc[mi][nj][2]), "+f"(acc[mi][nj][3])
                        : "r"(a[mi][0]), "r"(a[mi][1]), "r"(a[mi][2]), "r"(a[mi][3]),
                          "r"(b0), "r"(b1));
                }
        }
    }
    #pragma unroll
    for (int mi = 0; mi < 2; mi++)
        #pragma unroll
        for (int nj = 0; nj < 8; nj++) {
            int col = wn + nj * 8 + 2 * (lane & 3);
            #pragma unroll
            for (int h = 0; h < 2; h++) {
                int r = row0 + wm + mi * 16 + (lane >> 2) + h * 8;
                if (r < NN) {
                    float dn = g_dinv[r];
                    float v0 = acc[mi][nj][2 * h + 0] * dn;
                    float v1 = acc[mi][nj][2 * h + 1] * dn;
                    ((__half2*)g_h2h)[(r * 128 + col) >> 1] = __floats2half2_rn(v0, v1);
                }
            }
        }
}

// ---------------- layer-2 aggregation: a2h = fp16(relu(S @ h2 + b2)) ---------
__global__ void __launch_bounds__(256) k_agg128(const float* __restrict__ bias) {
    int node = (blockIdx.x * 256 + threadIdx.x) >> 5;
    int lane = threadIdx.x & 31;
    if (node >= NN) return;
    float dn = g_dinv[node];
    uint2 sv = ((const uint2*)g_h2h)[node * 32 + lane];
    float2 s0 = __half22float2(*(__half2*)&sv.x);
    float2 s1 = __half22float2(*(__half2*)&sv.y);
    float4 acc = make_float4(s0.x, s0.y, s1.x, s1.y);
    int e   = g_rowptr[node];
    int end = g_rowptr[node + 1];
    #pragma unroll 4
    for (; e < end; e++) {
        unsigned rec = __ldg(&g_edge[e]);
        int src  = rec & 0xFFFFu;
        float w  = __half2float(__ushort_as_half((unsigned short)(rec >> 16)));
        uint2 hv = ((const uint2*)g_h2h)[src * 32 + lane];
        float2 f0 = __half22float2(*(__half2*)&hv.x);
        float2 f1 = __half22float2(*(__half2*)&hv.y);
        acc.x += f0.x * w; acc.y += f0.y * w;
        acc.z += f1.x * w; acc.w += f1.y * w;
    }
    float4 b = ((const float4*)bias)[lane];
    acc.x = fmaxf(acc.x * dn + b.x, 0.f);
    acc.y = fmaxf(acc.y * dn + b.y, 0.f);
    acc.z = fmaxf(acc.z * dn + b.z, 0.f);
    acc.w = fmaxf(acc.w * dn + b.w, 0.f);
    uint2 pk;
    __half2 h0 = __floats2half2_rn(acc.x, acc.y);
    __half2 h1 = __floats2half2_rn(acc.z, acc.w);
    pk.x = *(unsigned*)&h0;
    pk.y = *(unsigned*)&h1;
    ((uint2*)g_a2h)[node * 32 + lane] = pk;
}

// ---------------- fused pool (sorted batch -> contiguous ranges) + MLP head --
__global__ void __launch_bounds__(128) k_poolmlp(const float* __restrict__ Wm1,
                                                 const float* __restrict__ bm1,
                                                 const float* __restrict__ Wm2,
                                                 const float* __restrict__ bm2,
                                                 float* __restrict__ out) {
    int g = blockIdx.x;
    int tid = threadIdx.x;
    __shared__ float ps[HID];
    __shared__ float zs[HID];
    int n0 = g_gptr[g], n1 = g_gptr[g + 1];
    float acc = 0.f;
    for (int n = n0; n < n1; n++)
        acc += __half2float(g_a2h[n * HID + tid]);
    ps[tid] = acc;
    __syncthreads();
    float z = bm1[tid];
    #pragma unroll 8
    for (int k = 0; k < HID; k++) z += ps[k] * Wm1[k * HID + tid];
    zs[tid] = fmaxf(z, 0.f);
    __syncthreads();
    if (tid < OUTD) {
        float a = bm2[tid];
        #pragma unroll 8
        for (int k = 0; k < HID; k++) a += zs[k] * Wm2[k * OUTD + tid];
        out[g * OUTD + tid] = a;
    }
}

// ---------------- launch ----------------
extern "C" void kernel_launch(void* const* d_in, const int* in_sizes, int n_in,
                              void* d_out, int out_size) {
    const float* x   = (const float*)d_in[0];
    const void*  ei  = d_in[1];
    const void*  bt  = d_in[2];
    const float* ew  = (const float*)d_in[3];
    const float* W1  = (const float*)d_in[4];
    const float* b1  = (const float*)d_in[5];
    const float* W2  = (const float*)d_in[6];
    const float* b2  = (const float*)d_in[7];
    const float* Wm1 = (const float*)d_in[8];
    const float* bm1 = (const float*)d_in[9];
    const float* Wm2 = (const float*)d_in[10];
    const float* bm2 = (const float*)d_in[11];
    float* out = (float*)d_out;

    k_histpre<<<(NE + 255) / 256, 256>>>(ei, bt, ew, x, W1, W2);
    k_scan<<<NBLK, SCAN_B>>>();
    k_scatter<<<(NE + 255) / 256, 256>>>(ei);
    k_aggx<<<(NN / 4 * 32 + 255) / 256, 256>>>();
    k_gemmf<<<(NN + 127) / 128, 256>>>(b1);
    k_agg128<<<(NN * 32 + 255) / 256, 256>>>(b2);
    k_poolmlp<<<NG, 128>>>(Wm1, bm1, Wm2, bm2, out);
}